// round 11
// baseline (speedup 1.0000x reference)
#include <cuda_runtime.h>
#include <cuda_bf16.h>
#include <cstdint>

// Problem constants
#define NPIX   16384       // B*H*W = 4*64*64
#define KSTEPS 72          // 9 taps * 8 k32-steps

// Scratch (allocation-free: __device__ globals)
__device__ int4   g_midx[9 * NPIX];          // corner element offsets (pre-multiplied by C)
__device__ float4 g_mw[9 * NPIX];            // bilinear*mask*valid weights
// Main-filter B operand, split bf16 hi/lo: [kstep][f(256)][ch(32)]
__device__ __nv_bfloat16 g_wbhi[KSTEPS * 256 * 32];
__device__ __nv_bfloat16 g_wblo[KSTEPS * 256 * 32];
// Offset-conv B operand, split bf16 hi/lo: [kstep][o(32, 27 used)][ch(32)]
__device__ __nv_bfloat16 g_obhi[KSTEPS * 32 * 32];
__device__ __nv_bfloat16 g_oblo[KSTEPS * 32 * 32];

__device__ __forceinline__ uint32_t smem_u32(const void* p) {
    uint32_t a;
    asm("{ .reg .u64 t; cvta.to.shared.u64 t, %1; cvt.u32.u64 %0, t; }" : "=r"(a) : "l"(p));
    return a;
}
#define CP_ASYNC16(dst_u32, src_ptr) \
    asm volatile("cp.async.cg.shared.global [%0], [%1], 16;" :: "r"(dst_u32), "l"(src_ptr))
#define CP_COMMIT()  asm volatile("cp.async.commit_group;" ::: "memory")
#define CP_WAIT1()   asm volatile("cp.async.wait_group 1;" ::: "memory")

// split one fp32 -> packed bf16 hi/lo helper
__device__ __forceinline__ void split_bf16(float s, uint16_t& h, uint16_t& l) {
    __nv_bfloat16 hb = __float2bfloat16(s);
    __nv_bfloat16 lb = __float2bfloat16(s - __bfloat162float(hb));
    h = __bfloat16_as_ushort(hb);
    l = __bfloat16_as_ushort(lb);
}

// ---------------------------------------------------------------------------
// Kernel 1: split filt [F,C,3,3] -> bf16 hi/lo in [kstep][f][32] layout
// ---------------------------------------------------------------------------
__global__ void split_filt_kernel(const float* __restrict__ filt) {
    int i = blockIdx.x * 256 + threadIdx.x;    // 9*256*256
    int c  = i & 255;
    int f  = (i >> 8) & 255;
    int kk = i >> 16;
    float w = filt[(f * 256 + c) * 9 + kk];
    uint16_t h, l;
    split_bf16(w, h, l);
    int kstep = kk * 8 + (c >> 5);
    int idx   = (kstep * 256 + f) * 32 + (c & 31);
    g_wbhi[idx] = __ushort_as_bfloat16(h);
    g_wblo[idx] = __ushort_as_bfloat16(l);
}

// ---------------------------------------------------------------------------
// Kernel 1b: split w_offset [3,3,256,27] -> [kstep][o(32)][ch(32)] hi/lo
// ---------------------------------------------------------------------------
__global__ void split_woff_kernel(const float* __restrict__ w_off) {
    int i = blockIdx.x * 256 + threadIdx.x;    // 72*32*32 = 73728
    int ch = i & 31;
    int o  = (i >> 5) & 31;
    int ks = i >> 10;
    int tap = ks >> 3;
    int c   = (ks & 7) * 32 + ch;
    float w = (o < 27) ? w_off[(tap * 256 + c) * 27 + o] : 0.f;
    uint16_t h, l;
    split_bf16(w, h, l);
    g_obhi[i] = __ushort_as_bfloat16(h);
    g_oblo[i] = __ushort_as_bfloat16(l);
}

// ---------------------------------------------------------------------------
// Kernel 2: offset conv as tensor-core GEMM + fused metadata epilogue.
// (unchanged from R10 winner)
// ---------------------------------------------------------------------------
#define OA_ST   16384
#define OB_BASE 32768
#define OB_ST   4096
#define OEPI    45056
#define OSMEM   63488

__global__ __launch_bounds__(256, 1)
void offset_gemm_kernel(const float* __restrict__ x, const float* __restrict__ b_off) {
    extern __shared__ char smraw[];
    char* smp = smraw;
    const uint32_t smb = smem_u32(smraw);

    const int tid  = threadIdx.x;
    const int wid  = tid >> 5;
    const int lane = tid & 31;
    const int p0   = blockIdx.x * 128;

    const int gpx  = tid >> 1;
    const int ghalf = tid & 1;
    const int gp   = p0 + gpx;
    const int gb   = gp >> 12;
    const int gy   = (gp >> 6) & 63;
    const int gx   = gp & 63;

    const int ar  = lane & 15;
    const int a16 = lane >> 4;
    const int br  = lane & 7;
    const int b1  = (lane >> 3) & 1;

#define OCOPY_B(ks, st) do {                                                        \
        int _half = tid >> 7;                                                       \
        int _t = tid & 127;                                                         \
        int _row = _t >> 2, _ch4 = _t & 3;                                          \
        const __nv_bfloat16* _src = (_half ? g_oblo : g_obhi) + (ks) * 1024 + _row * 32 + _ch4 * 8; \
        uint32_t _d = smb + OB_BASE + (st) * OB_ST + _half * 2048                   \
                      + _row * 64 + ((_ch4 ^ ((_row >> 1) & 3)) << 4);              \
        CP_ASYNC16(_d, (const char*)_src);                                          \
    } while (0)

#define OALDG(ksn, V) do {                                                          \
        const int _tap = (ksn) >> 3;                                                \
        const int _ki = _tap / 3, _kj = _tap - _ki * 3;                             \
        const int _ys = gy - 1 + _ki, _xs = gx - 1 + _kj;                           \
        if ((unsigned)_ys < 64u && (unsigned)_xs < 64u) {                           \
            const int _c = ((ksn) & 7) * 32 + ghalf * 16;                           \
            const float* _p = x + ((((gb << 12) + (_ys << 6) + _xs) << 8) + _c);    \
            V[0] = __ldg((const float4*)_p);                                        \
            V[1] = __ldg((const float4*)(_p + 4));                                  \
            V[2] = __ldg((const float4*)(_p + 8));                                  \
            V[3] = __ldg((const float4*)(_p + 12));                                 \
        } else {                                                                    \
            V[0] = V[1] = V[2] = V[3] = make_float4(0.f, 0.f, 0.f, 0.f);            \
        }                                                                           \
    } while (0)

#define OASTS(st, V) do {                                                           \
        uint32_t Vh[8], Vl[8];                                                      \
        _Pragma("unroll")                                                           \
        for (int _j = 0; _j < 4; ++_j) {                                            \
            uint16_t _h0,_l0,_h1,_l1,_h2,_l2,_h3,_l3;                               \
            split_bf16(V[_j].x, _h0, _l0); split_bf16(V[_j].y, _h1, _l1);           \
            split_bf16(V[_j].z, _h2, _l2); split_bf16(V[_j].w, _h3, _l3);           \
            Vh[_j * 2 + 0] = (uint32_t)_h0 | ((uint32_t)_h1 << 16);                 \
            Vh[_j * 2 + 1] = (uint32_t)_h2 | ((uint32_t)_h3 << 16);                 \
            Vl[_j * 2 + 0] = (uint32_t)_l0 | ((uint32_t)_l1 << 16);                 \
            Vl[_j * 2 + 1] = (uint32_t)_l2 | ((uint32_t)_l3 << 16);                 \
        }                                                                           \
        char* _dbase = smp + (st) * OA_ST + gpx * 64;                               \
        _Pragma("unroll")                                                           \
        for (int _q = 0; _q < 2; ++_q) {                                            \
            int _chunk = ghalf * 2 + _q;                                            \
            char* _d = _dbase + ((_chunk ^ ((gpx >> 1) & 3)) << 4);                 \
            *(uint4*)_d          = make_uint4(Vh[_q*4+0], Vh[_q*4+1], Vh[_q*4+2], Vh[_q*4+3]); \
            *(uint4*)(_d + 8192) = make_uint4(Vl[_q*4+0], Vl[_q*4+1], Vl[_q*4+2], Vl[_q*4+3]); \
        }                                                                           \
    } while (0)

    OCOPY_B(0, 0); CP_COMMIT();
    OCOPY_B(1, 1); CP_COMMIT();
    {
        float4 V[4];
        OALDG(0, V);
        OASTS(0, V);
    }
    CP_WAIT1();
    __syncthreads();

    float acc[4][4];
#pragma unroll
    for (int n = 0; n < 4; ++n)
#pragma unroll
        for (int q = 0; q < 4; ++q) acc[n][q] = 0.f;

#define OMMA(c, A0,A1,A2,A3,B0,B1) \
    asm volatile("mma.sync.aligned.m16n8k16.row.col.f32.bf16.bf16.f32 " \
        "{%0,%1,%2,%3}, {%4,%5,%6,%7}, {%8,%9}, {%0,%1,%2,%3};" \
        : "+f"((c)[0]), "+f"((c)[1]), "+f"((c)[2]), "+f"((c)[3]) \
        : "r"(A0), "r"(A1), "r"(A2), "r"(A3), "r"(B0), "r"(B1))

    for (int ks = 0; ks < KSTEPS; ++ks) {
        const uint32_t astg = smb + (ks & 1) * OA_ST;
        const uint32_t bstg = smb + OB_BASE + (ks % 3) * OB_ST;
        const bool more = (ks + 1 < KSTEPS);

        uint32_t ah[2][4], al[2][4], bh[2][4][2], bl[2][4][2];
#pragma unroll
        for (int ko = 0; ko < 2; ++ko) {
            int arow = wid * 16 + ar;
            uint32_t aaddr = astg + arow * 64 +
                (uint32_t)(((ko * 2 + a16) ^ ((arow >> 1) & 3)) << 4);
            asm volatile("ldmatrix.sync.aligned.m8n8.x4.shared.b16 {%0,%1,%2,%3}, [%4];"
                : "=r"(ah[ko][0]), "=r"(ah[ko][1]), "=r"(ah[ko][2]), "=r"(ah[ko][3])
                : "r"(aaddr));
            asm volatile("ldmatrix.sync.aligned.m8n8.x4.shared.b16 {%0,%1,%2,%3}, [%4];"
                : "=r"(al[ko][0]), "=r"(al[ko][1]), "=r"(al[ko][2]), "=r"(al[ko][3])
                : "r"(aaddr + 8192u));
#pragma unroll
            for (int n = 0; n < 4; ++n) {
                int brow = n * 8 + br;
                uint32_t baddr = bstg + brow * 64 +
                    (uint32_t)(((ko * 2 + b1) ^ ((brow >> 1) & 3)) << 4);
                asm volatile("ldmatrix.sync.aligned.m8n8.x2.shared.b16 {%0,%1}, [%2];"
                    : "=r"(bh[ko][n][0]), "=r"(bh[ko][n][1]) : "r"(baddr));
                asm volatile("ldmatrix.sync.aligned.m8n8.x2.shared.b16 {%0,%1}, [%2];"
                    : "=r"(bl[ko][n][0]), "=r"(bl[ko][n][1]) : "r"(baddr + 2048u));
            }
        }

        float4 V[4];
        if (more) OALDG(ks + 1, V);

#pragma unroll
        for (int ko = 0; ko < 2; ++ko) {
#pragma unroll
            for (int n = 0; n < 4; ++n)
                OMMA(acc[n], ah[ko][0], ah[ko][1], ah[ko][2], ah[ko][3], bh[ko][n][0], bh[ko][n][1]);
#pragma unroll
            for (int n = 0; n < 4; ++n)
                OMMA(acc[n], al[ko][0], al[ko][1], al[ko][2], al[ko][3], bh[ko][n][0], bh[ko][n][1]);
#pragma unroll
            for (int n = 0; n < 4; ++n)
                OMMA(acc[n], ah[ko][0], ah[ko][1], ah[ko][2], ah[ko][3], bl[ko][n][0], bl[ko][n][1]);
        }

        if (more) OASTS((ks + 1) & 1, V);
        if (ks + 2 < KSTEPS) OCOPY_B(ks + 2, (ks + 2) % 3);
        CP_COMMIT();
        CP_WAIT1();
        __syncthreads();
    }
#undef OMMA

    // ---- epilogue: acc -> smem [128][36] ----
    float* epi = (float*)(smp + OEPI);
    {
        const int r0 = wid * 16 + (lane >> 2);
#pragma unroll
        for (int n = 0; n < 4; ++n) {
            const int col = n * 8 + (lane & 3) * 2;
            epi[r0 * 36 + col]           = acc[n][0];
            epi[r0 * 36 + col + 1]       = acc[n][1];
            epi[(r0 + 8) * 36 + col]     = acc[n][2];
            epi[(r0 + 8) * 36 + col + 1] = acc[n][3];
        }
    }
    __syncthreads();

    // ---- metadata: 128 px x 9 taps ----
    for (int i = tid; i < 1152; i += 256) {
        int px = i / 9;
        int kk = i - px * 9;
        int gpix = p0 + px;
        int bb = gpix >> 12;
        int yy = (gpix >> 6) & 63;
        int xx = gpix & 63;

        float o1v = epi[px * 36 + kk]      + __ldg(b_off + kk);
        float o2v = epi[px * 36 + 9 + kk]  + __ldg(b_off + 9 + kk);
        float mlg = epi[px * 36 + 18 + kk] + __ldg(b_off + 18 + kk);
        float mv  = 1.f / (1.f + __expf(-mlg));

        float pyv = o1v + (float)(yy - 1 + kk / 3);
        float pxv = o2v + (float)(xx - 1 + kk % 3);
        float yf = floorf(pyv), xf = floorf(pxv);
        float dy = pyv - yf, dx = pxv - xf;
        int iy = (int)yf, ix = (int)xf;

        int base = bb << 12;
        int yc0 = min(max(iy, 0), 63),     yc1 = min(max(iy + 1, 0), 63);
        int xc0 = min(max(ix, 0), 63),     xc1 = min(max(ix + 1, 0), 63);
        float vy0 = ((unsigned)iy       < 64u) ? 1.f : 0.f;
        float vy1 = ((unsigned)(iy + 1) < 64u) ? 1.f : 0.f;
        float vx0 = ((unsigned)ix       < 64u) ? 1.f : 0.f;
        float vx1 = ((unsigned)(ix + 1) < 64u) ? 1.f : 0.f;

        g_midx[kk * NPIX + gpix] = make_int4(((base + (yc0 << 6) + xc0) << 8),
                                             ((base + (yc0 << 6) + xc1) << 8),
                                             ((base + (yc1 << 6) + xc0) << 8),
                                             ((base + (yc1 << 6) + xc1) << 8));
        g_mw[kk * NPIX + gpix] = make_float4((1.f - dy) * (1.f - dx) * mv * vy0 * vx0,
                                             (1.f - dy) * dx         * mv * vy0 * vx1,
                                             dy         * (1.f - dx) * mv * vy1 * vx0,
                                             dy         * dx         * mv * vy1 * vx1);
    }
}

// ---------------------------------------------------------------------------
// Kernel 3: FUSED gather + bf16 GEMM, register-trimmed schedule:
//  - B fragments loaded transiently per pass/per n (frees ~30 regs -> no spill)
//  - gather LDGs issued at iteration top / after STS(half0); STS after full ko
// ---------------------------------------------------------------------------
#define OFF_ALO 8192
#define OFF_BHI 16384
#define OFF_BLO 32768
#define STAGE_B 49152
#define NSTG    3
#define META_OFF (NSTG * STAGE_B)                    // 147456
#define SMEM_BYTES (META_OFF + 1152 * 16 * 2)        // 184320

__global__ __launch_bounds__(256, 1)
void dcn_gemm_kernel(const float* __restrict__ x, float* __restrict__ out) {
    extern __shared__ char smraw[];
    char* smp = smraw;
    const uint32_t smb = smem_u32(smraw);

    int4*   mi_s = (int4*)(smp + META_OFF);
    float4* mw_s = (float4*)(mi_s + 1152);

    const int tid  = threadIdx.x;
    const int wid  = tid >> 5;
    const int lane = tid & 31;
    const int p0   = blockIdx.x * 128;
    const int wp   = wid >> 2;
    const int wf   = wid & 3;

    const int gpx = tid >> 2;
    const int gcq = tid & 3;

    const int ar  = lane & 15;
    const int a16 = lane >> 4;
    const int br  = lane & 7;
    const int b1  = (lane >> 3) & 1;

    for (int i = tid; i < 1152; i += 256) {
        int kk = i >> 7, pp = i & 127;
        mi_s[i] = g_midx[kk * NPIX + p0 + pp];
        mw_s[i] = g_mw[kk * NPIX + p0 + pp];
    }

#define COPY_B(ks, st) do {                                                         \
        uint32_t _s = smb + (st) * STAGE_B + OFF_BHI;                               \
        _Pragma("unroll")                                                           \
        for (int _i = 0; _i < 4; ++_i) {                                            \
            int _idx = tid + _i * 256;                                              \
            int _row = _idx >> 2, _ch = _idx & 3;                                   \
            uint32_t _d = _s + _row * 64 + ((_ch ^ ((_row >> 1) & 3)) << 4);        \
            const char* _bh = (const char*)(g_wbhi + ((ks) * 256 + _row) * 32 + _ch * 8); \
            const char* _bl = (const char*)(g_wblo + ((ks) * 256 + _row) * 32 + _ch * 8); \
            CP_ASYNC16(_d, _bh);                                                    \
            CP_ASYNC16(_d + (OFF_BLO - OFF_BHI), _bl);                              \
        }                                                                           \
    } while (0)

#define GATHER_LDG(ksn, po, V) do {                                                 \
        const int _kk = (ksn) >> 3;                                                 \
        const int _cb = ((ksn) & 7) * 32;                                           \
        const int _px = (po) * 64 + gpx;                                            \
        const int4 _mi = mi_s[_kk * 128 + _px];                                     \
        _Pragma("unroll")                                                           \
        for (int _j = 0; _j < 2; ++_j) {                                            \
            const int _c = _cb + gcq * 8 + _j * 4;                                  \
            V[_j * 4 + 0] = __ldg((const float4*)(x + _mi.x + _c));                 \
            V[_j * 4 + 1] = __ldg((const float4*)(x + _mi.y + _c));                 \
            V[_j * 4 + 2] = __ldg((const float4*)(x + _mi.z + _c));                 \
            V[_j * 4 + 3] = __ldg((const float4*)(x + _mi.w + _c));                 \
        }                                                                           \
    } while (0)

#define GATHER_STS(ksn, st, po, V) do {                                             \
        const int _kk = (ksn) >> 3;                                                 \
        const int _px = (po) * 64 + gpx;                                            \
        const float4 _w = mw_s[_kk * 128 + _px];                                    \
        uint32_t _h[4], _l[4];                                                      \
        _Pragma("unroll")                                                           \
        for (int _j = 0; _j < 2; ++_j) {                                            \
            float4 _v00 = V[_j * 4 + 0], _v01 = V[_j * 4 + 1];                      \
            float4 _v10 = V[_j * 4 + 2], _v11 = V[_j * 4 + 3];                      \
            float _s0 = _v00.x * _w.x + _v01.x * _w.y + _v10.x * _w.z + _v11.x * _w.w; \
            float _s1 = _v00.y * _w.x + _v01.y * _w.y + _v10.y * _w.z + _v11.y * _w.w; \
            float _s2 = _v00.z * _w.x + _v01.z * _w.y + _v10.z * _w.z + _v11.z * _w.w; \
            float _s3 = _v00.w * _w.x + _v01.w * _w.y + _v10.w * _w.z + _v11.w * _w.w; \
            uint16_t _h0,_l0,_h1,_l1,_h2,_l2,_h3,_l3;                               \
            split_bf16(_s0, _h0, _l0); split_bf16(_s1, _h1, _l1);                   \
            split_bf16(_s2, _h2, _l2); split_bf16(_s3, _h3, _l3);                   \
            _h[_j * 2 + 0] = (uint32_t)_h0 | ((uint32_t)_h1 << 16);                 \
            _h[_j * 2 + 1] = (uint32_t)_h2 | ((uint32_t)_h3 << 16);                 \
            _l[_j * 2 + 0] = (uint32_t)_l0 | ((uint32_t)_l1 << 16);                 \
            _l[_j * 2 + 1] = (uint32_t)_l2 | ((uint32_t)_l3 << 16);                 \
        }                                                                           \
        char* _d = smp + (st) * STAGE_B + _px * 64 + ((gcq ^ ((_px >> 1) & 3)) << 4); \
        *(uint4*)_d             = make_uint4(_h[0], _h[1], _h[2], _h[3]);            \
        *(uint4*)(_d + OFF_ALO) = make_uint4(_l[0], _l[1], _l[2], _l[3]);            \
    } while (0)

    COPY_B(0, 0); CP_COMMIT();
    COPY_B(1, 1); CP_COMMIT();
    __syncthreads();
    {
        float4 V[8];
        GATHER_LDG(0, 0, V); GATHER_STS(0, 0, 0, V);
        GATHER_LDG(0, 1, V); GATHER_STS(0, 0, 1, V);
    }
    CP_WAIT1();
    __syncthreads();

    float acc[4][8][4];
#pragma unroll
    for (int m = 0; m < 4; ++m)
#pragma unroll
        for (int n = 0; n < 8; ++n)
#pragma unroll
            for (int q = 0; q < 4; ++q) acc[m][n][q] = 0.f;

// A fragments (hi+lo) for one ko
#define LOAD_AFRAGS(stg, ko)                                                         \
    _Pragma("unroll")                                                                \
    for (int m = 0; m < 4; ++m) {                                                    \
        int row = wp * 64 + m * 16 + ar;                                             \
        uint32_t aaddr = (stg) + row * 64 +                                          \
            (uint32_t)(((((ko) * 2 + a16) ^ ((row >> 1) & 3)) << 4));                \
        asm volatile("ldmatrix.sync.aligned.m8n8.x4.shared.b16 {%0,%1,%2,%3}, [%4];" \
            : "=r"(ah[m][0]), "=r"(ah[m][1]), "=r"(ah[m][2]), "=r"(ah[m][3])         \
            : "r"(aaddr));                                                           \
        asm volatile("ldmatrix.sync.aligned.m8n8.x4.shared.b16 {%0,%1,%2,%3}, [%4];" \
            : "=r"(al[m][0]), "=r"(al[m][1]), "=r"(al[m][2]), "=r"(al[m][3])         \
            : "r"(aaddr + (uint32_t)OFF_ALO));                                       \
    }

#define MMA(c, A0,A1,A2,A3,B0,B1) \
    asm volatile("mma.sync.aligned.m16n8k16.row.col.f32.bf16.bf16.f32 " \
        "{%0,%1,%2,%3}, {%4,%5,%6,%7}, {%8,%9}, {%0,%1,%2,%3};" \
        : "+f"((c)[0]), "+f"((c)[1]), "+f"((c)[2]), "+f"((c)[3]) \
        : "r"(A0), "r"(A1), "r"(A2), "r"(A3), "r"(B0), "r"(B1))

// one pass: B fragments loaded transiently per n (hi: boff=0, lo: boff=16384)
#define MMA_PASS_T(stg, ko, AF, boff)                                                \
    _Pragma("unroll")                                                                \
    for (int n = 0; n < 8; ++n) {                                                    \
        uint32_t b0_, b1_;                                                           \
        int row = wf * 64 + n * 8 + br;                                              \
        uint32_t baddr = (stg) + OFF_BHI + (boff) + row * 64 +                       \
            (uint32_t)(((((ko) * 2 + b1) ^ ((row >> 1) & 3)) << 4));                 \
        asm volatile("ldmatrix.sync.aligned.m8n8.x2.shared.b16 {%0,%1}, [%2];"       \
            : "=r"(b0_), "=r"(b1_) : "r"(baddr));                                    \
        _Pragma("unroll")                                                            \
        for (int m = 0; m < 4; ++m)                                                  \
            MMA(acc[m][n], AF[m][0], AF[m][1], AF[m][2], AF[m][3], b0_, b1_);        \
    }

    for (int ks = 0; ks < KSTEPS; ++ks) {
        const uint32_t stg = smb + (ks % NSTG) * STAGE_B;
        const int nst = (ks + 1) % NSTG;
        const bool more = (ks + 1 < KSTEPS);

        uint32_t ah[4][4], al[4][4];
        float4 V[8];

        // gather half0 loads issued at the very top -> max latency cover
        if (more) GATHER_LDG(ks + 1, 0, V);

        // ---- ko = 0 ----
        LOAD_AFRAGS(stg, 0)
        MMA_PASS_T(stg, 0, ah, 0)
        MMA_PASS_T(stg, 0, al, 0)
        MMA_PASS_T(stg, 0, ah, (OFF_BLO - OFF_BHI))
        if (more) {
            GATHER_STS(ks + 1, nst, 0, V);     // half0 landed during 3 passes
            GATHER_LDG(ks + 1, 1, V);          // half1 flies under ko=1
        }

        // ---- ko = 1 ----
        LOAD_AFRAGS(stg, 1)
        MMA_PASS_T(stg, 1, ah, 0)
        MMA_PASS_T(stg, 1, al, 0)
        MMA_PASS_T(stg, 1, ah, (OFF_BLO - OFF_BHI))
        if (more) GATHER_STS(ks + 1, nst, 1, V);

        if (ks + 2 < KSTEPS) { COPY_B(ks + 2, (ks + 2) % NSTG); }
        CP_COMMIT();
        CP_WAIT1();
        __syncthreads();
    }
#undef MMA_PASS_T
#undef MMA
#undef LOAD_AFRAGS

#pragma unroll
    for (int m = 0; m < 4; ++m) {
        const int r0 = p0 + wp * 64 + m * 16 + (lane >> 2);
#pragma unroll
        for (int n = 0; n < 8; ++n) {
            const int col = wf * 64 + n * 8 + (lane & 3) * 2;
            *(float2*)(out + r0 * 256 + col)       = make_float2(acc[m][n][0], acc[m][n][1]);
            *(float2*)(out + (r0 + 8) * 256 + col) = make_float2(acc[m][n][2], acc[m][n][3]);
        }
    }
}

// ---------------------------------------------------------------------------
extern "C" void kernel_launch(void* const* d_in, const int* in_sizes, int n_in,
                              void* d_out, int out_size) {
    const float* x     = (const float*)d_in[0];   // [4,64,64,256]
    const float* w_off = (const float*)d_in[1];   // [3,3,256,27]
    const float* b_off = (const float*)d_in[2];   // [27]
    const float* filt  = (const float*)d_in[3];   // [256,256,3,3]
    float* out = (float*)d_out;                   // [4,64,64,256]

    cudaFuncSetAttribute(dcn_gemm_kernel, cudaFuncAttributeMaxDynamicSharedMemorySize, SMEM_BYTES);
    cudaFuncSetAttribute(offset_gemm_kernel, cudaFuncAttributeMaxDynamicSharedMemorySize, OSMEM);

    split_filt_kernel<<<2304, 256>>>(filt);
    split_woff_kernel<<<288, 256>>>(w_off);
    offset_gemm_kernel<<<128, 256, OSMEM>>>(x, b_off);
    dcn_gemm_kernel<<<128, 256, SMEM_BYTES>>>(x, out);
}